// round 7
// baseline (speedup 1.0000x reference)
#include <cuda_runtime.h>
#include <cuda_fp16.h>
#include <cstdint>

// N=32768, D=128, K=1024. scores = ||c||^2 - 2 x.c
// Phase A (in-kernel): approx scores via single fp16 HMMA term (xh*ch, fp32 acc),
// per-lane top-3 candidate tracking.  Phase B (same kernel epilogue): exact fp32
// rescore of all candidates within W of the row's approx min; argmin via packed
// atomicMin (ties -> lowest index, matching reference).

#define DDIM     128
#define KCODES   1024
#define MT       128
#define NTILE    128
#define NT_CNT   (KCODES / NTILE)   // 8
#define NTHREADS 512
#define WINDOW   0.2f

__device__ __half g_cbh[KCODES * DDIM];
__device__ float  g_cnorm[KCODES];

// ---------------- SMEM layout (bytes) ----------------
// AH [128][128] half swizzled : 32KB @ 0
// B ring: 3 stages x 32KB @ 32768 (x fp32 prologue stage overlays stages 0-1)
// rowapprox[128] u64 @ 131072 ; rowbest[128] u64 @ 132096
#define SM_AH    0
#define SM_B     32768
#define SM_RAPP  131072
#define SM_RBEST 132096
#define SMEM_BYTES 133120

__device__ __forceinline__ uint32_t smem_u32(const void* p) {
    uint32_t a;
    asm("{ .reg .u64 t; cvta.to.shared.u64 t, %1; cvt.u32.u64 %0, t; }" : "=r"(a) : "l"(p));
    return a;
}
__device__ __forceinline__ void cp_async16(uint32_t dst, const void* src) {
    asm volatile("cp.async.cg.shared.global [%0], [%1], 16;" :: "r"(dst), "l"(src) : "memory");
}
__device__ __forceinline__ void cp_commit() {
    asm volatile("cp.async.commit_group;" ::: "memory");
}
template <int W>
__device__ __forceinline__ void cp_wait() {
    asm volatile("cp.async.wait_group %0;" :: "n"(W) : "memory");
}
__device__ __forceinline__ void ldsm4(uint32_t& r0, uint32_t& r1, uint32_t& r2, uint32_t& r3,
                                      uint32_t addr) {
    asm volatile("ldmatrix.sync.aligned.m8n8.x4.shared.b16 {%0,%1,%2,%3}, [%4];"
                 : "=r"(r0), "=r"(r1), "=r"(r2), "=r"(r3) : "r"(addr));
}
__device__ __forceinline__ void mma_f32(float* c, const uint32_t* a, uint32_t b0, uint32_t b1) {
    asm volatile(
        "mma.sync.aligned.m16n8k16.row.col.f32.f16.f16.f32 "
        "{%0,%1,%2,%3}, {%4,%5,%6,%7}, {%8,%9}, {%0,%1,%2,%3};"
        : "+f"(c[0]), "+f"(c[1]), "+f"(c[2]), "+f"(c[3])
        : "r"(a[0]), "r"(a[1]), "r"(a[2]), "r"(a[3]), "r"(b0), "r"(b1));
}
__device__ __forceinline__ uint32_t fp_order(float f) {
    uint32_t u = __float_as_uint(f);
    return u ^ ((u >> 31) ? 0xFFFFFFFFu : 0x80000000u);
}
__device__ __forceinline__ float fp_unorder(uint32_t e) {
    uint32_t u = (e >> 31) ? (e ^ 0x80000000u) : ~e;
    return __uint_as_float(u);
}
__device__ __forceinline__ void ins3(unsigned long long* b, unsigned long long p) {
    if (p < b[0])      { b[2] = b[1]; b[1] = b[0]; b[0] = p; }
    else if (p < b[1]) { b[2] = b[1]; b[1] = p; }
    else if (p < b[2]) { b[2] = p; }
}

// ---------------- prep: fp16 codebook + norms ----------------
__global__ void prep_kernel(const float* __restrict__ cb) {
    int k = blockIdx.x, d = threadIdx.x;
    float v = cb[k * DDIM + d];
    g_cbh[k * DDIM + d] = __float2half_rn(v);
    float s = v * v;
#pragma unroll
    for (int o = 16; o; o >>= 1) s += __shfl_xor_sync(~0u, s, o);
    __shared__ float ws[4];
    if ((threadIdx.x & 31) == 0) ws[threadIdx.x >> 5] = s;
    __syncthreads();
    if (threadIdx.x == 0) g_cnorm[k] = ws[0] + ws[1] + ws[2] + ws[3];
}

extern __shared__ char smem[];

__device__ __forceinline__ void issue_b_tile(uint32_t sb, int nt, int st, int tid) {
#pragma unroll
    for (int i = 0; i < 4; i++) {
        int ch  = i * NTHREADS + tid;          // 2048 chunks of 16B
        int row = ch >> 4;
        int c16 = ch & 15;
        const __half* src = g_cbh + ((size_t)(nt * NTILE + row) * DDIM + c16 * 8);
        uint32_t dst = sb + SM_B + (uint32_t)st * 32768u
                     + (uint32_t)(row * 16 + (c16 ^ (row & 7))) * 16u;
        cp_async16(dst, src);
    }
    cp_commit();
}

__global__ __launch_bounds__(NTHREADS, 1) void vq_mma_kernel(
    const float* __restrict__ x, const float* __restrict__ cb, float* __restrict__ out)
{
    const uint32_t sb = smem_u32(smem);
    const int tid  = threadIdx.x;
    const int lane = tid & 31;
    const int warp = tid >> 5;
    const int wm   = warp >> 2;        // 0..3 : rows wm*32..+31
    const int wn   = warp & 3;         // 0..3 : cols wn*32..+31
    const int m0   = blockIdx.x * MT;

    unsigned long long* rowapprox = reinterpret_cast<unsigned long long*>(smem + SM_RAPP);
    unsigned long long* rowbest   = reinterpret_cast<unsigned long long*>(smem + SM_RBEST);

    // ---- prologue: stage x fp32 (contiguous tile), convert hi half to AH smem ----
    {
        const float4* xsrc = reinterpret_cast<const float4*>(x + (size_t)m0 * DDIM);
        float4* xstage = reinterpret_cast<float4*>(smem + SM_B);
#pragma unroll
        for (int i = 0; i < 8; i++) xstage[i * NTHREADS + tid] = xsrc[i * NTHREADS + tid];
        __syncthreads();
        const float* xs = reinterpret_cast<const float*>(smem + SM_B);
#pragma unroll
        for (int i = 0; i < 4; i++) {
            int oc  = i * NTHREADS + tid;       // 2048 fp16 chunks (16B = 8 halfs)
            int row = oc >> 4;
            int hc  = oc & 15;
            const float* p = xs + row * DDIM + hc * 8;
            uint32_t hi[4];
#pragma unroll
            for (int j = 0; j < 4; j++) {
                __half h0 = __float2half_rn(p[j * 2]);
                __half h1 = __float2half_rn(p[j * 2 + 1]);
                hi[j] = ((uint32_t)__half_as_ushort(h1) << 16) | __half_as_ushort(h0);
            }
            uint32_t chunk = (uint32_t)(row * 16 + (hc ^ (row & 7))) * 16u;
            *reinterpret_cast<uint4*>(smem + SM_AH + chunk) = make_uint4(hi[0], hi[1], hi[2], hi[3]);
        }
        if (tid < MT) { rowapprox[tid] = ~0ull; rowbest[tid] = ~0ull; }
        __syncthreads();   // x-stage (B region) free for prefetch
    }

    issue_b_tile(sb, 0, 0, tid);
    issue_b_tile(sb, 1, 1, tid);
    issue_b_tile(sb, 2, 2, tid);

    // per-lane top-3 per row-slot (4 slots: mi*2+h)
    unsigned long long top[4][3];
#pragma unroll
    for (int s = 0; s < 4; s++) { top[s][0] = ~0ull; top[s][1] = ~0ull; top[s][2] = ~0ull; }

    const int t8 = lane >> 3;
    const int j8 = lane & 7;

    for (int nt = 0; nt < NT_CNT; nt++) {
        if (nt < NT_CNT - 2)       cp_wait<2>();
        else if (nt == NT_CNT - 2) cp_wait<1>();
        else                       cp_wait<0>();
        __syncthreads();
        const int st = nt % 3;
        const uint32_t bhb = sb + SM_B + (uint32_t)st * 32768u;

        float acc[2][4][4];
#pragma unroll
        for (int mi = 0; mi < 2; mi++)
#pragma unroll
            for (int ni = 0; ni < 4; ni++)
#pragma unroll
                for (int c = 0; c < 4; c++) acc[mi][ni][c] = 0.f;

#pragma unroll
        for (int kc = 0; kc < 8; kc++) {
            const int c16 = kc * 2 + (t8 >> 1);
            uint32_t ah[2][4];
#pragma unroll
            for (int mi = 0; mi < 2; mi++) {
                int row = wm * 32 + mi * 16 + (t8 & 1) * 8 + j8;
                uint32_t off = (uint32_t)(row * 16 + (c16 ^ (row & 7))) * 16u;
                ldsm4(ah[mi][0], ah[mi][1], ah[mi][2], ah[mi][3], sb + SM_AH + off);
            }
            uint32_t bh[2][4];
#pragma unroll
            for (int bi = 0; bi < 2; bi++) {
                int nrow = wn * 32 + bi * 16 + (t8 & 1) * 8 + j8;
                uint32_t off = (uint32_t)(nrow * 16 + (c16 ^ (nrow & 7))) * 16u;
                ldsm4(bh[bi][0], bh[bi][1], bh[bi][2], bh[bi][3], bhb + off);
            }
#pragma unroll
            for (int mi = 0; mi < 2; mi++)
#pragma unroll
                for (int ni = 0; ni < 4; ni++) {
                    int bi = ni >> 1, sub = ni & 1;
                    mma_f32(acc[mi][ni], ah[mi], bh[bi][sub], bh[bi][sub + 2]);
                }
        }

        // ---- fold approx scores into per-lane top-3 ----
#pragma unroll
        for (int ni = 0; ni < 4; ni++) {
            int col0 = nt * NTILE + wn * 32 + ni * 8 + 2 * (lane & 3);
            float cn0 = __ldg(&g_cnorm[col0]);
            float cn1 = __ldg(&g_cnorm[col0 + 1]);
#pragma unroll
            for (int mi = 0; mi < 2; mi++) {
                float s00 = fmaf(-2.f, acc[mi][ni][0], cn0);
                float s01 = fmaf(-2.f, acc[mi][ni][1], cn1);
                float s10 = fmaf(-2.f, acc[mi][ni][2], cn0);
                float s11 = fmaf(-2.f, acc[mi][ni][3], cn1);
                ins3(top[mi * 2],     ((unsigned long long)fp_order(s00) << 32) | (uint32_t)col0);
                ins3(top[mi * 2],     ((unsigned long long)fp_order(s01) << 32) | (uint32_t)(col0 + 1));
                ins3(top[mi * 2 + 1], ((unsigned long long)fp_order(s10) << 32) | (uint32_t)col0);
                ins3(top[mi * 2 + 1], ((unsigned long long)fp_order(s11) << 32) | (uint32_t)(col0 + 1));
            }
        }

        __syncthreads();   // all warps done with stage st before overwrite
        if (nt + 3 < NT_CNT) issue_b_tile(sb, nt + 3, st, tid);
    }

    // ---- stage 1: approx row minimum ----
#pragma unroll
    for (int s = 0; s < 4; s++) {
        int row = wm * 32 + (s >> 1) * 16 + (s & 1) * 8 + (lane >> 2);
        atomicMin(&rowapprox[row], top[s][0]);
    }
    __syncthreads();

    // ---- stage 2: exact rescore of candidates within WINDOW of approx min ----
#pragma unroll
    for (int s = 0; s < 4; s++) {
        int row = wm * 32 + (s >> 1) * 16 + (s & 1) * 8 + (lane >> 2);
        float thr = fp_unorder((uint32_t)(rowapprox[row] >> 32)) + WINDOW;
#pragma unroll
        for (int j = 0; j < 3; j++) {
            unsigned long long p = top[s][j];
            if (p == ~0ull) continue;
            float sa = fp_unorder((uint32_t)(p >> 32));
            if (sa >= thr) continue;
            int idx = (int)(p & 0xFFFFFFFFu);
            const float4* xr = reinterpret_cast<const float4*>(x + (size_t)(m0 + row) * DDIM);
            const float4* cr = reinterpret_cast<const float4*>(cb + (size_t)idx * DDIM);
            float dot = 0.f;
#pragma unroll
            for (int q = 0; q < 32; q++) {
                float4 a = xr[q], b = cr[q];
                dot = fmaf(a.x, b.x, dot);
                dot = fmaf(a.y, b.y, dot);
                dot = fmaf(a.z, b.z, dot);
                dot = fmaf(a.w, b.w, dot);
            }
            float se = fmaf(-2.f, dot, __ldg(&g_cnorm[idx]));
            atomicMin(&rowbest[row], ((unsigned long long)fp_order(se) << 32) | (uint32_t)idx);
        }
    }
    __syncthreads();

    // ---- output: out = x + (q - x), coalesced float4 ----
    const float4* x4  = reinterpret_cast<const float4*>(x);
    const float4* cb4 = reinterpret_cast<const float4*>(cb);
    float4* o4 = reinterpret_cast<float4*>(out);
#pragma unroll
    for (int i = 0; i < 8; i++) {
        int g  = i * NTHREADS + tid;            // 4096 float4
        int r  = g >> 5, c4 = g & 31;
        int bi = (int)(rowbest[r] & 0xFFFFFFFFu);
        float4 xv = x4[(size_t)(m0 + r) * 32 + c4];
        float4 qv = cb4[(size_t)bi * 32 + c4];
        float4 ov;
        ov.x = xv.x + (qv.x - xv.x);
        ov.y = xv.y + (qv.y - xv.y);
        ov.z = xv.z + (qv.z - xv.z);
        ov.w = xv.w + (qv.w - xv.w);
        o4[(size_t)(m0 + r) * 32 + c4] = ov;
    }
}

extern "C" void kernel_launch(void* const* d_in, const int* in_sizes, int n_in,
                              void* d_out, int out_size) {
    const float* x  = (const float*)d_in[0];
    const float* cb = (const float*)d_in[1];
    float* out = (float*)d_out;
    int N = in_sizes[0] / DDIM;     // 32768
    int K = in_sizes[1] / DDIM;     // 1024

    prep_kernel<<<K, DDIM>>>(cb);

    cudaFuncSetAttribute(vq_mma_kernel, cudaFuncAttributeMaxDynamicSharedMemorySize, SMEM_BYTES);
    vq_mma_kernel<<<N / MT, NTHREADS, SMEM_BYTES>>>(x, cb, out);
}